// round 1
// baseline (speedup 1.0000x reference)
#include <cuda_runtime.h>
#include <cuda_bf16.h>
#include <math.h>

// Problem constants (from reference setup_inputs)
#define BATCH 8192
#define DIM   512
#define HID   2048
#define HV    512
#define VO    256

// ---------------------------------------------------------------------------
// Device-global scratch (no cudaMalloc allowed)
// ---------------------------------------------------------------------------
__device__ float g_H1[BATCH * HID];     // tanh(x@W1+b1)        64 MB
__device__ float g_FH[BATCH * DIM];     // fhatx                16 MB
__device__ float g_HX[BATCH * HV];      // tanh(x@Wv1)          16 MB
__device__ float g_Yx[BATCH * VO];      // HX@Wv2                8 MB
__device__ float g_U [BATCH * HV];      // fhatx@Wv1            16 MB
__device__ float g_tgt[BATCH];          // 0.99*V(x)
__device__ float g_s  [BATCH];          // ||fhatx||^2 per row
__device__ float g_alpha[BATCH];

// ---------------------------------------------------------------------------
// Tiled SGEMM: C = epi(A@B [+bias]).  BM=BN=128, BK=8, TM=TN=8, 256 thr.
// EPI bit0 = tanh, bit1 = bias
// ---------------------------------------------------------------------------
template <int EPI>
__global__ __launch_bounds__(256) void sgemm128(
    int M, int N, int K,
    const float* __restrict__ A, const float* __restrict__ B,
    const float* __restrict__ bias, float* __restrict__ C)
{
    const int BM = 128, BN = 128, BK = 8, TM = 8, TN = 8;
    __shared__ float As[BK * BM];   // stored transposed: As[k][m]
    __shared__ float Bs[BK * BN];

    const int cRow = blockIdx.y;
    const int cCol = blockIdx.x;

    A += (size_t)cRow * BM * K;
    B += cCol * BN;
    C += (size_t)cRow * BM * N + cCol * BN;
    const float* biasp = bias + cCol * BN;

    const int threadCol = threadIdx.x % (BN / TN);   // 0..15
    const int threadRow = threadIdx.x / (BN / TN);   // 0..15
    const int innerRowA = threadIdx.x / (BK / 4);    // 0..127
    const int innerColA = threadIdx.x % (BK / 4);    // 0..1
    const int innerRowB = threadIdx.x / (BN / 4);    // 0..7
    const int innerColB = threadIdx.x % (BN / 4);    // 0..31

    float acc[TM * TN];
    #pragma unroll
    for (int i = 0; i < TM * TN; i++) acc[i] = 0.0f;
    float regM[TM], regN[TN];

    for (int bk = 0; bk < K; bk += BK) {
        float4 ta = *reinterpret_cast<const float4*>(A + innerRowA * K + innerColA * 4);
        As[(innerColA * 4 + 0) * BM + innerRowA] = ta.x;
        As[(innerColA * 4 + 1) * BM + innerRowA] = ta.y;
        As[(innerColA * 4 + 2) * BM + innerRowA] = ta.z;
        As[(innerColA * 4 + 3) * BM + innerRowA] = ta.w;
        *reinterpret_cast<float4*>(Bs + innerRowB * BN + innerColB * 4) =
            *reinterpret_cast<const float4*>(B + innerRowB * N + innerColB * 4);
        __syncthreads();

        A += BK;
        B += (size_t)BK * N;

        #pragma unroll
        for (int k = 0; k < BK; k++) {
            #pragma unroll
            for (int i = 0; i < TM; i++) regM[i] = As[k * BM + threadRow * TM + i];
            #pragma unroll
            for (int j = 0; j < TN; j++) regN[j] = Bs[k * BN + threadCol * TN + j];
            #pragma unroll
            for (int i = 0; i < TM; i++)
                #pragma unroll
                for (int j = 0; j < TN; j++)
                    acc[i * TN + j] += regM[i] * regN[j];
        }
        __syncthreads();
    }

    // epilogue
    #pragma unroll
    for (int i = 0; i < TM; i++) {
        int row = threadRow * TM + i;
        #pragma unroll
        for (int j = 0; j < TN; j += 4) {
            int col = threadCol * TN + j;
            float4 v;
            v.x = acc[i * TN + j + 0];
            v.y = acc[i * TN + j + 1];
            v.z = acc[i * TN + j + 2];
            v.w = acc[i * TN + j + 3];
            if (EPI & 2) {
                v.x += biasp[col + 0];
                v.y += biasp[col + 1];
                v.z += biasp[col + 2];
                v.w += biasp[col + 3];
            }
            if (EPI & 1) {
                v.x = tanhf(v.x); v.y = tanhf(v.y);
                v.z = tanhf(v.z); v.w = tanhf(v.w);
            }
            *reinterpret_cast<float4*>(C + (size_t)row * N + col) = v;
        }
    }
}

// ---------------------------------------------------------------------------
// Row reductions: target[b] = 0.99*(sum Yx^2 + 0.01*sum x^2); s[b] = sum FH^2
// one warp per row
// ---------------------------------------------------------------------------
__device__ __forceinline__ float warpsum(float v) {
    #pragma unroll
    for (int o = 16; o > 0; o >>= 1) v += __shfl_down_sync(0xFFFFFFFFu, v, o);
    return v;
}

__global__ void reduce_kernel(const float* __restrict__ x,
                              const float* __restrict__ Yx,
                              const float* __restrict__ FH,
                              float* __restrict__ tgt,
                              float* __restrict__ s)
{
    int wid = threadIdx.x >> 5, lane = threadIdx.x & 31;
    int row = blockIdx.x * 8 + wid;
    float sy = 0.f, sx = 0.f, sf = 0.f;
    const float* yr = Yx + (size_t)row * VO;
    const float* xr = x  + (size_t)row * DIM;
    const float* fr = FH + (size_t)row * DIM;
    for (int j = lane; j < VO; j += 32) { float v = yr[j]; sy += v * v; }
    for (int d = lane; d < DIM; d += 32) {
        float v = xr[d]; sx += v * v;
        float f = fr[d]; sf += f * f;
    }
    sy = warpsum(sy); sx = warpsum(sx); sf = warpsum(sf);
    if (lane == 0) {
        tgt[row] = 0.99f * (sy + 0.01f * sx);
        s[row]   = sf;
    }
}

// ---------------------------------------------------------------------------
// Persistent per-sample Newton rootfind.
//   V(a) = ||tanh(a*u)@Wv2||^2 + 0.01*a^2*s
//   dV/da = 2*y.( ((1-h^2)*u)@Wv2 ) + 0.02*a*s
// Each block handles NG samples; 256 threads = VO columns of Wv2.
// Exactly reproduces the reference masked while-loop (per-sample convergence,
// cap 50 Newton updates).
// ---------------------------------------------------------------------------
#define NG 8
__global__ __launch_bounds__(256) void newton_kernel(
    const float* __restrict__ U, const float* __restrict__ Wv2,
    const float* __restrict__ s_arr, const float* __restrict__ tgt_arr,
    float* __restrict__ alpha_out)
{
    __shared__ float sh_h[NG][HV];
    __shared__ float sh_u[NG][HV];
    __shared__ float sh_part[8][NG];
    __shared__ float sh_alpha[NG], sh_resid[NG], sh_s[NG], sh_tgt[NG];
    __shared__ int   sh_active[NG], sh_upd[NG], sh_any;

    const int tid  = threadIdx.x;
    const int lane = tid & 31, wid = tid >> 5;
    const int base = blockIdx.x * NG;

    // load u rows (float4)
    for (int idx = tid; idx < NG * (HV / 4); idx += 256) {
        int sI = idx >> 7, v = idx & 127;
        reinterpret_cast<float4*>(sh_u[sI])[v] =
            reinterpret_cast<const float4*>(U + (size_t)(base + sI) * HV)[v];
    }
    if (tid < NG) {
        sh_alpha[tid]  = 1.0f;
        sh_active[tid] = 1;
        sh_s[tid]   = s_arr[base + tid];
        sh_tgt[tid] = tgt_arr[base + tid];
    }
    __syncthreads();

    for (int it = 0; it < 50; it++) {
        // h = tanh(alpha * u) for active samples
        for (int idx = tid; idx < NG * HV; idx += 256) {
            int sI = idx >> 9, k = idx & (HV - 1);
            if (sh_active[sI]) sh_h[sI][k] = tanhf(sh_alpha[sI] * sh_u[sI][k]);
        }
        __syncthreads();

        // pass 1: y_j per sample, then Vz = sum y^2
        float accY[NG];
        #pragma unroll
        for (int s2 = 0; s2 < NG; s2++) accY[s2] = 0.f;
        const int j = tid;  // 256 threads == VO columns
        for (int k = 0; k < HV; k += 4) {
            float w0 = Wv2[(k + 0) * VO + j];
            float w1 = Wv2[(k + 1) * VO + j];
            float w2 = Wv2[(k + 2) * VO + j];
            float w3 = Wv2[(k + 3) * VO + j];
            #pragma unroll
            for (int s2 = 0; s2 < NG; s2++) {
                float4 hv = *reinterpret_cast<const float4*>(&sh_h[s2][k]);
                accY[s2] += hv.x * w0 + hv.y * w1 + hv.z * w2 + hv.w * w3;
            }
        }
        #pragma unroll
        for (int s2 = 0; s2 < NG; s2++) {
            float v = warpsum(accY[s2] * accY[s2]);
            if (lane == 0) sh_part[wid][s2] = v;
        }
        __syncthreads();
        if (tid < NG) {
            sh_upd[tid] = 0;
            if (sh_active[tid]) {
                float Vz = 0.f;
                #pragma unroll
                for (int w = 0; w < 8; w++) Vz += sh_part[w][tid];
                float a = sh_alpha[tid];
                Vz += 0.01f * a * a * sh_s[tid];
                float resid = Vz - sh_tgt[tid];
                if (resid > 1e-3f) { sh_upd[tid] = 1; sh_resid[tid] = resid; }
                else               sh_active[tid] = 0;
            }
        }
        __syncthreads();
        if (tid == 0) {
            int a = 0;
            #pragma unroll
            for (int s2 = 0; s2 < NG; s2++) a |= sh_upd[s2];
            sh_any = a;
        }
        __syncthreads();
        if (!sh_any) break;

        // pass 2: w_j = ((1-h^2)*u)@Wv2 ; dot = sum y_j*w_j
        float accW[NG];
        #pragma unroll
        for (int s2 = 0; s2 < NG; s2++) accW[s2] = 0.f;
        for (int k = 0; k < HV; k += 4) {
            float w0 = Wv2[(k + 0) * VO + j];
            float w1 = Wv2[(k + 1) * VO + j];
            float w2 = Wv2[(k + 2) * VO + j];
            float w3 = Wv2[(k + 3) * VO + j];
            #pragma unroll
            for (int s2 = 0; s2 < NG; s2++) {
                float4 hv = *reinterpret_cast<const float4*>(&sh_h[s2][k]);
                float4 uv = *reinterpret_cast<const float4*>(&sh_u[s2][k]);
                accW[s2] += (1.f - hv.x * hv.x) * uv.x * w0
                          + (1.f - hv.y * hv.y) * uv.y * w1
                          + (1.f - hv.z * hv.z) * uv.z * w2
                          + (1.f - hv.w * hv.w) * uv.w * w3;
            }
        }
        #pragma unroll
        for (int s2 = 0; s2 < NG; s2++) {
            float v = warpsum(accY[s2] * accW[s2]);
            if (lane == 0) sh_part[wid][s2] = v;
        }
        __syncthreads();
        if (tid < NG && sh_upd[tid]) {
            float dot = 0.f;
            #pragma unroll
            for (int w = 0; w < 8; w++) dot += sh_part[w][tid];
            float a   = sh_alpha[tid];
            float dVda = 2.f * dot + 0.02f * a * sh_s[tid];
            sh_alpha[tid] = a - sh_resid[tid] / dVda;
        }
        __syncthreads();
    }

    if (tid < NG) alpha_out[base + tid] = sh_alpha[tid];
}

// ---------------------------------------------------------------------------
// out = FH * alpha (row-broadcast)
// ---------------------------------------------------------------------------
__global__ void scale_out_kernel(const float* __restrict__ FH,
                                 const float* __restrict__ alpha,
                                 float* __restrict__ out)
{
    int i = blockIdx.x * blockDim.x + threadIdx.x;   // float4 index
    const int total4 = BATCH * (DIM / 4);
    if (i < total4) {
        float a = alpha[i >> 7];                      // DIM/4 = 128 float4/row
        float4 v = reinterpret_cast<const float4*>(FH)[i];
        v.x *= a; v.y *= a; v.z *= a; v.w *= a;
        reinterpret_cast<float4*>(out)[i] = v;
    }
}

// ---------------------------------------------------------------------------
extern "C" void kernel_launch(void* const* d_in, const int* in_sizes, int n_in,
                              void* d_out, int out_size)
{
    const float* x   = (const float*)d_in[0];
    const float* W1  = (const float*)d_in[1];
    const float* b1  = (const float*)d_in[2];
    const float* W2  = (const float*)d_in[3];
    const float* b2  = (const float*)d_in[4];
    const float* Wv1 = (const float*)d_in[5];
    const float* Wv2 = (const float*)d_in[6];
    float* out = (float*)d_out;

    float *H1, *FH, *HX, *Yx, *U, *tgt, *s, *alpha;
    cudaGetSymbolAddress((void**)&H1,    g_H1);
    cudaGetSymbolAddress((void**)&FH,    g_FH);
    cudaGetSymbolAddress((void**)&HX,    g_HX);
    cudaGetSymbolAddress((void**)&Yx,    g_Yx);
    cudaGetSymbolAddress((void**)&U,     g_U);
    cudaGetSymbolAddress((void**)&tgt,   g_tgt);
    cudaGetSymbolAddress((void**)&s,     g_s);
    cudaGetSymbolAddress((void**)&alpha, g_alpha);

    dim3 blk(256);

    // H1 = tanh(x@W1 + b1)                 (8192 x 2048, K=512)
    sgemm128<3><<<dim3(HID / 128, BATCH / 128), blk>>>(BATCH, HID, DIM, x, W1, b1, H1);
    // FH = H1@W2 + b2                      (8192 x 512, K=2048)
    sgemm128<2><<<dim3(DIM / 128, BATCH / 128), blk>>>(BATCH, DIM, HID, H1, W2, b2, FH);
    // HX = tanh(x@Wv1)                     (8192 x 512, K=512)
    sgemm128<1><<<dim3(HV / 128, BATCH / 128), blk>>>(BATCH, HV, DIM, x, Wv1, nullptr, HX);
    // Yx = HX@Wv2                          (8192 x 256, K=512)
    sgemm128<0><<<dim3(VO / 128, BATCH / 128), blk>>>(BATCH, VO, HV, HX, Wv2, nullptr, Yx);
    // U = FH@Wv1                           (8192 x 512, K=512)
    sgemm128<0><<<dim3(HV / 128, BATCH / 128), blk>>>(BATCH, HV, DIM, FH, Wv1, nullptr, U);

    // target & ||fhatx||^2
    reduce_kernel<<<BATCH / 8, blk>>>(x, Yx, FH, tgt, s);

    // per-sample Newton rootfind (expected: converges at alpha=1, one pass)
    newton_kernel<<<BATCH / NG, blk>>>(U, Wv2, s, tgt, alpha);

    // out = fhatx * alpha
    scale_out_kernel<<<(BATCH * (DIM / 4) + 255) / 256, blk>>>(FH, alpha, out);
}

// round 4
// speedup vs baseline: 2.3144x; 2.3144x over previous
#include <cuda_runtime.h>
#include <cuda_bf16.h>
#include <stdint.h>
#include <math.h>

// Problem constants
#define BATCH 8192
#define DIM   512
#define HID   2048
#define HV    512
#define VO    256

// ---------------------------------------------------------------------------
// Device-global scratch (no cudaMalloc allowed)
// ---------------------------------------------------------------------------
__device__ __align__(256) float g_H1[BATCH * HID];
__device__ __align__(256) float g_FH[BATCH * DIM];
__device__ __align__(256) float g_HX[BATCH * HV];
__device__ __align__(256) float g_Yx[BATCH * VO];
__device__ __align__(256) float g_U [BATCH * HV];
__device__ __align__(256) float g_tgt[BATCH];
__device__ __align__(256) float g_s  [BATCH];
__device__ __align__(256) float g_alpha[BATCH];

// weights: transposed to [N,K] + split into bf16 hi/lo
__device__ __align__(256) __nv_bfloat16 g_W1t_hi[HID * DIM];
__device__ __align__(256) __nv_bfloat16 g_W1t_lo[HID * DIM];
__device__ __align__(256) __nv_bfloat16 g_W2t_hi[DIM * HID];
__device__ __align__(256) __nv_bfloat16 g_W2t_lo[DIM * HID];
__device__ __align__(256) __nv_bfloat16 g_Wv1t_hi[HV * DIM];
__device__ __align__(256) __nv_bfloat16 g_Wv1t_lo[HV * DIM];
__device__ __align__(256) __nv_bfloat16 g_Wv2t_hi[VO * HV];
__device__ __align__(256) __nv_bfloat16 g_Wv2t_lo[VO * HV];

// ---------------------------------------------------------------------------
// Helpers
// ---------------------------------------------------------------------------
__device__ __forceinline__ uint32_t smem_u32(const void* p) {
    uint32_t a;
    asm("{ .reg .u64 t; cvta.to.shared.u64 t, %1; cvt.u32.u64 %0, t; }"
        : "=r"(a) : "l"(p));
    return a;
}
__device__ __forceinline__ void ldsm4(uint32_t* r, uint32_t addr) {
    asm volatile("ldmatrix.sync.aligned.m8n8.x4.shared.b16 {%0,%1,%2,%3}, [%4];"
                 : "=r"(r[0]), "=r"(r[1]), "=r"(r[2]), "=r"(r[3]) : "r"(addr));
}
__device__ __forceinline__ void mma_bf16(float* c, const uint32_t* a, const uint32_t* b) {
    asm volatile("mma.sync.aligned.m16n8k16.row.col.f32.bf16.bf16.f32 "
                 "{%0,%1,%2,%3}, {%4,%5,%6,%7}, {%8,%9}, {%0,%1,%2,%3};"
                 : "+f"(c[0]), "+f"(c[1]), "+f"(c[2]), "+f"(c[3])
                 : "r"(a[0]), "r"(a[1]), "r"(a[2]), "r"(a[3]),
                   "r"(b[0]), "r"(b[1]));
}
// SMEM swizzle for 64-byte rows (32 bf16): chunk = 16B unit
__device__ __forceinline__ uint32_t sw_off(int row, int kc) {
    return (uint32_t)(row * 64 + (((kc) ^ ((row >> 1) & 3)) << 4));
}
__device__ __forceinline__ uint32_t pack_bf2(float a, float b) {
    __nv_bfloat162 h = __floats2bfloat162_rn(a, b);
    return *reinterpret_cast<uint32_t*>(&h);
}

// ---------------------------------------------------------------------------
// Weight transpose + hi/lo split: W[K,N] row-major -> hi/lo[N,K]
// ---------------------------------------------------------------------------
__global__ void tsplit_kernel(const float* __restrict__ W, int K, int N,
                              __nv_bfloat16* __restrict__ hi,
                              __nv_bfloat16* __restrict__ lo)
{
    __shared__ float t[32][33];
    int n0 = blockIdx.x * 32, k0 = blockIdx.y * 32;
    int tx = threadIdx.x, ty = threadIdx.y;   // 32 x 8
    #pragma unroll
    for (int i = 0; i < 32; i += 8)
        t[ty + i][tx] = W[(size_t)(k0 + ty + i) * N + n0 + tx];
    __syncthreads();
    #pragma unroll
    for (int i = 0; i < 32; i += 8) {
        float v = t[tx][ty + i];
        __nv_bfloat16 h = __float2bfloat16_rn(v);
        float rem = v - __bfloat162float(h);
        hi[(size_t)(n0 + ty + i) * K + k0 + tx] = h;
        lo[(size_t)(n0 + ty + i) * K + k0 + tx] = __float2bfloat16_rn(rem);
    }
}

// ---------------------------------------------------------------------------
// mma.sync GEMM: C[M,N] = epi(A @ Bt^T [+bias]), error-compensated bf16.
//   A  : fp32 [M,K] row-major, split into bf16 hi/lo on the fly
//   Bt : bf16 hi/lo [N,K] row-major (pre-split)
// Block tile 128x128, BK=32, 8 warps (4m x 2n), warp tile 32x64,
// double-buffered SMEM, register prefetch.  EPI bit0=tanh, bit1=bias.
// ---------------------------------------------------------------------------
#define BKT   32
#define S_AHI 0
#define S_ALO 8192
#define S_BHI 16384
#define S_BLO 24576
#define STG   32768
#define SMEM_TOTAL (2 * STG)

template <int EPI>
__global__ __launch_bounds__(256, 1) void tgemm(
    int N, int K,
    const float* __restrict__ A,
    const __nv_bfloat16* __restrict__ Bhi,
    const __nv_bfloat16* __restrict__ Blo,
    const float* __restrict__ bias,
    float* __restrict__ C)
{
    extern __shared__ char smem[];
    const uint32_t sb = smem_u32(smem);
    const int tid = threadIdx.x, lane = tid & 31, wid = tid >> 5;
    const int wm = wid & 3, wn = wid >> 2;
    const int m0 = blockIdx.y * 128, n0 = blockIdx.x * 128;
    const int nk = K / BKT;

    float acc[2][8][4];
    #pragma unroll
    for (int i = 0; i < 2; i++)
        #pragma unroll
        for (int j = 0; j < 8; j++)
            #pragma unroll
            for (int q = 0; q < 4; q++) acc[i][j][q] = 0.f;

    // prefetch registers: 2 tasks/thread; task idx -> row=idx>>2, kc=idx&3
    float4 ra[2][2];
    uint4  rbh[2], rbl[2];

    const int t_row0 = tid >> 2,          t_kc0 = tid & 3;
    const int t_row1 = (tid + 256) >> 2,  t_kc1 = tid & 3;  // idx+256: kc same, row+64

    // prologue: load chunk 0
    {
        const float* ap0 = A + (size_t)(m0 + t_row0) * K + t_kc0 * 8;
        const float* ap1 = A + (size_t)(m0 + t_row1) * K + t_kc1 * 8;
        ra[0][0] = *reinterpret_cast<const float4*>(ap0);
        ra[0][1] = *reinterpret_cast<const float4*>(ap0 + 4);
        ra[1][0] = *reinterpret_cast<const float4*>(ap1);
        ra[1][1] = *reinterpret_cast<const float4*>(ap1 + 4);
        const __nv_bfloat16* bh0 = Bhi + (size_t)(n0 + t_row0) * K + t_kc0 * 8;
        const __nv_bfloat16* bh1 = Bhi + (size_t)(n0 + t_row1) * K + t_kc1 * 8;
        const __nv_bfloat16* bl0 = Blo + (size_t)(n0 + t_row0) * K + t_kc0 * 8;
        const __nv_bfloat16* bl1 = Blo + (size_t)(n0 + t_row1) * K + t_kc1 * 8;
        rbh[0] = *reinterpret_cast<const uint4*>(bh0);
        rbh[1] = *reinterpret_cast<const uint4*>(bh1);
        rbl[0] = *reinterpret_cast<const uint4*>(bl0);
        rbl[1] = *reinterpret_cast<const uint4*>(bl1);
    }

    for (int c = 0; c < nk; c++) {
        const int buf = c & 1;
        char* sp = smem + buf * STG;
        const uint32_t sbase = sb + buf * STG;

        // store prefetched chunk into SMEM stage
        #pragma unroll
        for (int t = 0; t < 2; t++) {
            const int row = t ? t_row1 : t_row0;
            const int kc  = t ? t_kc1  : t_kc0;
            const uint32_t off = sw_off(row, kc);
            float4 v0 = ra[t][0], v1 = ra[t][1];
            __nv_bfloat16 h0 = __float2bfloat16_rn(v0.x);
            __nv_bfloat16 h1 = __float2bfloat16_rn(v0.y);
            __nv_bfloat16 h2 = __float2bfloat16_rn(v0.z);
            __nv_bfloat16 h3 = __float2bfloat16_rn(v0.w);
            __nv_bfloat16 h4 = __float2bfloat16_rn(v1.x);
            __nv_bfloat16 h5 = __float2bfloat16_rn(v1.y);
            __nv_bfloat16 h6 = __float2bfloat16_rn(v1.z);
            __nv_bfloat16 h7 = __float2bfloat16_rn(v1.w);
            uint4 hv;
            hv.x = pack_bf2(v0.x, v0.y); hv.y = pack_bf2(v0.z, v0.w);
            hv.z = pack_bf2(v1.x, v1.y); hv.w = pack_bf2(v1.z, v1.w);
            uint4 lv;
            lv.x = pack_bf2(v0.x - __bfloat162float(h0), v0.y - __bfloat162float(h1));
            lv.y = pack_bf2(v0.z - __bfloat162float(h2), v0.w - __bfloat162float(h3));
            lv.z = pack_bf2(v1.x - __bfloat162float(h4), v1.y - __bfloat162float(h5));
            lv.w = pack_bf2(v1.z - __bfloat162float(h6), v1.w - __bfloat162float(h7));
            *reinterpret_cast<uint4*>(sp + S_AHI + off) = hv;
            *reinterpret_cast<uint4*>(sp + S_ALO + off) = lv;
            *reinterpret_cast<uint4*>(sp + S_BHI + off) = rbh[t];
            *reinterpret_cast<uint4*>(sp + S_BLO + off) = rbl[t];
        }
        __syncthreads();

        // prefetch next chunk (global latency overlaps compute)
        if (c + 1 < nk) {
            const int k0 = (c + 1) * BKT;
            const float* ap0 = A + (size_t)(m0 + t_row0) * K + k0 + t_kc0 * 8;
            const float* ap1 = A + (size_t)(m0 + t_row1) * K + k0 + t_kc1 * 8;
            ra[0][0] = *reinterpret_cast<const float4*>(ap0);
            ra[0][1] = *reinterpret_cast<const float4*>(ap0 + 4);
            ra[1][0] = *reinterpret_cast<const float4*>(ap1);
            ra[1][1] = *reinterpret_cast<const float4*>(ap1 + 4);
            const __nv_bfloat16* bh0 = Bhi + (size_t)(n0 + t_row0) * K + k0 + t_kc0 * 8;
            const __nv_bfloat16* bh1 = Bhi + (size_t)(n0 + t_row1) * K + k0 + t_kc1 * 8;
            const __nv_bfloat16* bl0 = Blo + (size_t)(n0 + t_row0) * K + k0 + t_kc0 * 8;
            const __nv_bfloat16* bl1 = Blo + (size_t)(n0 + t_row1) * K + k0 + t_kc1 * 8;
            rbh[0] = *reinterpret_cast<const uint4*>(bh0);
            rbh[1] = *reinterpret_cast<const uint4*>(bh1);
            rbl[0] = *reinterpret_cast<const uint4*>(bl0);
            rbl[1] = *reinterpret_cast<const uint4*>(bl1);
        }

        // compute on current stage
        #pragma unroll
        for (int k16 = 0; k16 < 2; k16++) {
            uint32_t ah[2][4], al[2][4];
            #pragma unroll
            for (int mt = 0; mt < 2; mt++) {
                int r  = wm * 32 + mt * 16 + (lane & 15);
                int kc = k16 * 2 + (lane >> 4);
                uint32_t off = sw_off(r, kc);
                ldsm4(ah[mt], sbase + S_AHI + off);
                ldsm4(al[mt], sbase + S_ALO + off);
            }
            #pragma unroll
            for (int g = 0; g < 4; g++) {
                int r  = wn * 64 + g * 16 + ((lane >> 4) << 3) + (lane & 7);
                int kc = k16 * 2 + ((lane >> 3) & 1);
                uint32_t off = sw_off(r, kc);
                uint32_t bh[4], bl[4];
                ldsm4(bh, sbase + S_BHI + off);
                ldsm4(bl, sbase + S_BLO + off);
                #pragma unroll
                for (int mt = 0; mt < 2; mt++) {
                    #pragma unroll
                    for (int h = 0; h < 2; h++) {
                        float* cc = acc[mt][g * 2 + h];
                        mma_bf16(cc, ah[mt], bh + h * 2);
                        mma_bf16(cc, ah[mt], bl + h * 2);
                        mma_bf16(cc, al[mt], bh + h * 2);
                    }
                }
            }
        }
    }

    // epilogue
    #pragma unroll
    for (int mt = 0; mt < 2; mt++) {
        #pragma unroll
        for (int nt = 0; nt < 8; nt++) {
            int row = m0 + wm * 32 + mt * 16 + (lane >> 2);
            int col = n0 + wn * 64 + nt * 8 + (lane & 3) * 2;
            float b0 = 0.f, b1 = 0.f;
            if (EPI & 2) { b0 = __ldg(bias + col); b1 = __ldg(bias + col + 1); }
            float v0 = acc[mt][nt][0] + b0, v1 = acc[mt][nt][1] + b1;
            float v2 = acc[mt][nt][2] + b0, v3 = acc[mt][nt][3] + b1;
            if (EPI & 1) { v0 = tanhf(v0); v1 = tanhf(v1); v2 = tanhf(v2); v3 = tanhf(v3); }
            *reinterpret_cast<float2*>(C + (size_t)row * N + col) = make_float2(v0, v1);
            *reinterpret_cast<float2*>(C + (size_t)(row + 8) * N + col) = make_float2(v2, v3);
        }
    }
}

// ---------------------------------------------------------------------------
// Row reductions + Newton rootfind + output scale
// ---------------------------------------------------------------------------
__device__ __forceinline__ float warpsum(float v) {
    #pragma unroll
    for (int o = 16; o > 0; o >>= 1) v += __shfl_down_sync(0xFFFFFFFFu, v, o);
    return v;
}

__global__ void reduce_kernel(const float* __restrict__ x)
{
    int wid = threadIdx.x >> 5, lane = threadIdx.x & 31;
    int row = blockIdx.x * 8 + wid;
    float sy = 0.f, sx = 0.f, sf = 0.f;
    const float* yr = g_Yx + (size_t)row * VO;
    const float* xr = x    + (size_t)row * DIM;
    const float* fr = g_FH + (size_t)row * DIM;
    for (int j = lane; j < VO; j += 32) { float v = yr[j]; sy += v * v; }
    for (int d = lane; d < DIM; d += 32) {
        float v = xr[d]; sx += v * v;
        float f = fr[d]; sf += f * f;
    }
    sy = warpsum(sy); sx = warpsum(sx); sf = warpsum(sf);
    if (lane == 0) {
        g_tgt[row] = 0.99f * (sy + 0.01f * sx);
        g_s[row]   = sf;
    }
}

#define NG 8
__global__ __launch_bounds__(256) void newton_kernel(const float* __restrict__ Wv2)
{
    __shared__ float sh_h[NG][HV];
    __shared__ float sh_u[NG][HV];
    __shared__ float sh_part[8][NG];
    __shared__ float sh_alpha[NG], sh_resid[NG], sh_s[NG], sh_tgt[NG];
    __shared__ int   sh_active[NG], sh_upd[NG], sh_any;

    const int tid  = threadIdx.x;
    const int lane = tid & 31, wid = tid >> 5;
    const int base = blockIdx.x * NG;

    for (int idx = tid; idx < NG * (HV / 4); idx += 256) {
        int sI = idx >> 7, v = idx & 127;
        reinterpret_cast<float4*>(sh_u[sI])[v] =
            reinterpret_cast<const float4*>(g_U + (size_t)(base + sI) * HV)[v];
    }
    if (tid < NG) {
        sh_alpha[tid]  = 1.0f;
        sh_active[tid] = 1;
        sh_s[tid]   = g_s[base + tid];
        sh_tgt[tid] = g_tgt[base + tid];
    }
    __syncthreads();

    for (int it = 0; it < 50; it++) {
        for (int idx = tid; idx < NG * HV; idx += 256) {
            int sI = idx >> 9, k = idx & (HV - 1);
            if (sh_active[sI]) sh_h[sI][k] = tanhf(sh_alpha[sI] * sh_u[sI][k]);
        }
        __syncthreads();

        float accY[NG];
        #pragma unroll
        for (int s2 = 0; s2 < NG; s2++) accY[s2] = 0.f;
        const int j = tid;
        for (int k = 0; k < HV; k += 4) {
            float w0 = Wv2[(k + 0) * VO + j];
            float w1 = Wv2[(k + 1) * VO + j];
            float w2 = Wv2[(k + 2) * VO + j];
            float w3 = Wv2[(k + 3) * VO + j];
            #pragma unroll
            for (int s2 = 0; s2 < NG; s2++) {
                float4 hv = *reinterpret_cast<const float4*>(&sh_h[s2][k]);
                accY[s2] += hv.x * w0 + hv.y * w1 + hv.z * w2 + hv.w * w3;
            }
        }
        #pragma unroll
        for (int s2 = 0; s2 < NG; s2++) {
            float v = warpsum(accY[s2] * accY[s2]);
            if (lane == 0) sh_part[wid][s2] = v;
        }
        __syncthreads();
        if (tid < NG) {
            sh_upd[tid] = 0;
            if (sh_active[tid]) {
                float Vz = 0.f;
                #pragma unroll
                for (int w = 0; w < 8; w++) Vz += sh_part[w][tid];
                float a = sh_alpha[tid];
                Vz += 0.01f * a * a * sh_s[tid];
                float resid = Vz - sh_tgt[tid];
                if (resid > 1e-3f) { sh_upd[tid] = 1; sh_resid[tid] = resid; }
                else               sh_active[tid] = 0;
            }
        }
        __syncthreads();
        if (tid == 0) {
            int a = 0;
            #pragma unroll
            for (int s2 = 0; s2 < NG; s2++) a |= sh_upd[s2];
            sh_any = a;
        }
        __syncthreads();
        if (!sh_any) break;

        float accW[NG];
        #pragma unroll
        for (int s2 = 0; s2 < NG; s2++) accW[s2] = 0.f;
        for (int k = 0; k < HV; k += 4) {
            float w0 = Wv2[(k + 0) * VO + j];
            float w1 = Wv2[(k + 1) * VO + j];
            float w2 = Wv2[(k + 2) * VO + j];
            float w3 = Wv2[(k + 3) * VO + j];
            #pragma unroll
            for (int s2 = 0; s2 < NG; s2++) {
                float4 hv = *reinterpret_cast<const float4*>(&sh_h[s2][k]);
                float4 uv = *reinterpret_cast<const float4*>(&sh_u[s2][k]);
                accW[s2] += (1.f - hv.x * hv.x) * uv.x * w0
                          + (1.f - hv.y * hv.y) * uv.y * w1
                          + (1.f - hv.z * hv.z) * uv.z * w2
                          + (1.f - hv.w * hv.w) * uv.w * w3;
            }
        }
        #pragma unroll
        for (int s2 = 0; s2 < NG; s2++) {
            float v = warpsum(accY[s2] * accW[s2]);
            if (lane == 0) sh_part[wid][s2] = v;
        }
        __syncthreads();
        if (tid < NG && sh_upd[tid]) {
            float dot = 0.f;
            #pragma unroll
            for (int w = 0; w < 8; w++) dot += sh_part[w][tid];
            float a   = sh_alpha[tid];
            float dVda = 2.f * dot + 0.02f * a * sh_s[tid];
            sh_alpha[tid] = a - sh_resid[tid] / dVda;
        }
        __syncthreads();
    }

    if (tid < NG) g_alpha[base + tid] = sh_alpha[tid];
}

__global__ void scale_out_kernel(float* __restrict__ out)
{
    int i = blockIdx.x * blockDim.x + threadIdx.x;
    const int total4 = BATCH * (DIM / 4);
    if (i < total4) {
        float a = g_alpha[i >> 7];
        float4 v = reinterpret_cast<const float4*>(g_FH)[i];
        v.x *= a; v.y *= a; v.z *= a; v.w *= a;
        reinterpret_cast<float4*>(out)[i] = v;
    }
}

// ---------------------------------------------------------------------------
extern "C" void kernel_launch(void* const* d_in, const int* in_sizes, int n_in,
                              void* d_out, int out_size)
{
    const float* x   = (const float*)d_in[0];
    const float* W1  = (const float*)d_in[1];
    const float* b1  = (const float*)d_in[2];
    const float* W2  = (const float*)d_in[3];
    const float* b2  = (const float*)d_in[4];
    const float* Wv1 = (const float*)d_in[5];
    const float* Wv2 = (const float*)d_in[6];
    float* out = (float*)d_out;

    float* H1 = 0;  cudaGetSymbolAddress((void**)&H1, g_H1);
    float* FH = 0;  cudaGetSymbolAddress((void**)&FH, g_FH);
    float* HX = 0;  cudaGetSymbolAddress((void**)&HX, g_HX);
    float* Yx = 0;  cudaGetSymbolAddress((void**)&Yx, g_Yx);
    float* U  = 0;  cudaGetSymbolAddress((void**)&U,  g_U);
    __nv_bfloat16* W1h = 0; cudaGetSymbolAddress((void**)&W1h, g_W1t_hi);
    __nv_bfloat16* W1l = 0; cudaGetSymbolAddress((void**)&W1l, g_W1t_lo);
    __nv_bfloat16* W2h = 0; cudaGetSymbolAddress((void**)&W2h, g_W2t_hi);
    __nv_bfloat16* W2l = 0; cudaGetSymbolAddress((void**)&W2l, g_W2t_lo);
    __nv_bfloat16* V1h = 0; cudaGetSymbolAddress((void**)&V1h, g_Wv1t_hi);
    __nv_bfloat16* V1l = 0; cudaGetSymbolAddress((void**)&V1l, g_Wv1t_lo);
    __nv_bfloat16* V2h = 0; cudaGetSymbolAddress((void**)&V2h, g_Wv2t_hi);
    __nv_bfloat16* V2l = 0; cudaGetSymbolAddress((void**)&V2l, g_Wv2t_lo);

    cudaFuncSetAttribute(tgemm<0>, cudaFuncAttributeMaxDynamicSharedMemorySize, SMEM_TOTAL);
    cudaFuncSetAttribute(tgemm<1>, cudaFuncAttributeMaxDynamicSharedMemorySize, SMEM_TOTAL);
    cudaFuncSetAttribute(tgemm<2>, cudaFuncAttributeMaxDynamicSharedMemorySize, SMEM_TOTAL);
    cudaFuncSetAttribute(tgemm<3>, cudaFuncAttributeMaxDynamicSharedMemorySize, SMEM_TOTAL);

    dim3 tb(32, 8);
    // weight transpose + split
    tsplit_kernel<<<dim3(HID / 32, DIM / 32), tb>>>(W1,  DIM, HID, W1h, W1l);
    tsplit_kernel<<<dim3(DIM / 32, HID / 32), tb>>>(W2,  HID, DIM, W2h, W2l);
    tsplit_kernel<<<dim3(HV  / 32, DIM / 32), tb>>>(Wv1, DIM, HV,  V1h, V1l);
    tsplit_kernel<<<dim3(VO  / 32, HV  / 32), tb>>>(Wv2, HV,  VO,  V2h, V2l);

    // GEMMs (mma.sync bf16, error-compensated)
    tgemm<3><<<dim3(HID / 128, BATCH / 128), 256, SMEM_TOTAL>>>(HID, DIM, x,  W1h, W1l, b1, H1);
    tgemm<2><<<dim3(DIM / 128, BATCH / 128), 256, SMEM_TOTAL>>>(DIM, HID, H1, W2h, W2l, b2, FH);
    tgemm<1><<<dim3(HV  / 128, BATCH / 128), 256, SMEM_TOTAL>>>(HV,  DIM, x,  V1h, V1l, 0, HX);
    tgemm<0><<<dim3(VO  / 128, BATCH / 128), 256, SMEM_TOTAL>>>(VO,  HV,  HX, V2h, V2l, 0, Yx);
    tgemm<0><<<dim3(HV  / 128, BATCH / 128), 256, SMEM_TOTAL>>>(HV,  DIM, FH, V1h, V1l, 0, U);

    reduce_kernel<<<BATCH / 8, 256>>>(x);
    newton_kernel<<<BATCH / NG, 256>>>(Wv2);
    scale_out_kernel<<<(BATCH * (DIM / 4) + 255) / 256, 256>>>(out);
}

// round 5
// speedup vs baseline: 2.7616x; 1.1932x over previous
#include <cuda_runtime.h>
#include <cuda_bf16.h>
#include <stdint.h>
#include <math.h>

// Problem constants
#define BATCH 8192
#define DIM   512
#define HID   2048
#define HV    512
#define VO    256

// ---------------------------------------------------------------------------
// Device-global scratch (no cudaMalloc allowed)
// ---------------------------------------------------------------------------
__device__ __align__(256) float g_FH[BATCH * DIM];      // fhatx fp32
__device__ __align__(256) float g_Yx[BATCH * VO];
__device__ __align__(256) float g_U [BATCH * HV];
__device__ __align__(256) float g_tgt[BATCH];
__device__ __align__(256) float g_s  [BATCH];
__device__ __align__(256) float g_alpha[BATCH];

// activations, bf16 hi/lo
__device__ __align__(256) __nv_bfloat16 g_xhi[BATCH * DIM];
__device__ __align__(256) __nv_bfloat16 g_xlo[BATCH * DIM];
__device__ __align__(256) __nv_bfloat16 g_H1hi[BATCH * HID];
__device__ __align__(256) __nv_bfloat16 g_H1lo[BATCH * HID];
__device__ __align__(256) __nv_bfloat16 g_FHhi[BATCH * DIM];
__device__ __align__(256) __nv_bfloat16 g_FHlo[BATCH * DIM];
__device__ __align__(256) __nv_bfloat16 g_HXhi[BATCH * HV];

// weights: transposed to [N,K] + split into bf16 hi/lo
__device__ __align__(256) __nv_bfloat16 g_W1t_hi[HID * DIM];
__device__ __align__(256) __nv_bfloat16 g_W1t_lo[HID * DIM];
__device__ __align__(256) __nv_bfloat16 g_W2t_hi[DIM * HID];
__device__ __align__(256) __nv_bfloat16 g_W2t_lo[DIM * HID];
__device__ __align__(256) __nv_bfloat16 g_Wv1t_hi[HV * DIM];
__device__ __align__(256) __nv_bfloat16 g_Wv1t_lo[HV * DIM];
__device__ __align__(256) __nv_bfloat16 g_Wv2t_hi[VO * HV];
__device__ __align__(256) __nv_bfloat16 g_Wv2t_lo[VO * HV];

// ---------------------------------------------------------------------------
// Helpers
// ---------------------------------------------------------------------------
__device__ __forceinline__ uint32_t smem_u32(const void* p) {
    uint32_t a;
    asm("{ .reg .u64 t; cvta.to.shared.u64 t, %1; cvt.u32.u64 %0, t; }"
        : "=r"(a) : "l"(p));
    return a;
}
__device__ __forceinline__ void ldsm4(uint32_t* r, uint32_t addr) {
    asm volatile("ldmatrix.sync.aligned.m8n8.x4.shared.b16 {%0,%1,%2,%3}, [%4];"
                 : "=r"(r[0]), "=r"(r[1]), "=r"(r[2]), "=r"(r[3]) : "r"(addr));
}
__device__ __forceinline__ void mma_bf16(float* c, const uint32_t* a, const uint32_t* b) {
    asm volatile("mma.sync.aligned.m16n8k16.row.col.f32.bf16.bf16.f32 "
                 "{%0,%1,%2,%3}, {%4,%5,%6,%7}, {%8,%9}, {%0,%1,%2,%3};"
                 : "+f"(c[0]), "+f"(c[1]), "+f"(c[2]), "+f"(c[3])
                 : "r"(a[0]), "r"(a[1]), "r"(a[2]), "r"(a[3]),
                   "r"(b[0]), "r"(b[1]));
}
__device__ __forceinline__ void cpa16(uint32_t dst, const void* src) {
    asm volatile("cp.async.cg.shared.global [%0], [%1], 16;" :: "r"(dst), "l"(src));
}
#define CP_COMMIT() asm volatile("cp.async.commit_group;" ::: "memory")
#define CP_WAIT(n)  asm volatile("cp.async.wait_group %0;" :: "n"(n) : "memory")

// SMEM swizzle for 64-byte rows (32 bf16): chunk = 16B unit
__device__ __forceinline__ uint32_t sw_off(int row, int kc) {
    return (uint32_t)(row * 64 + (((kc) ^ ((row >> 1) & 3)) << 4));
}
__device__ __forceinline__ uint32_t pack_bf2(float a, float b) {
    __nv_bfloat162 h = __floats2bfloat162_rn(a, b);
    return *reinterpret_cast<uint32_t*>(&h);
}
__device__ __forceinline__ float bf_hi(float v) {
    return __bfloat162float(__float2bfloat16_rn(v));
}

// ---------------------------------------------------------------------------
// Weight transpose + hi/lo split: W[K,N] row-major -> hi/lo[N,K]
// ---------------------------------------------------------------------------
__global__ void tsplit_kernel(const float* __restrict__ W, int K, int N,
                              __nv_bfloat16* __restrict__ hi,
                              __nv_bfloat16* __restrict__ lo)
{
    __shared__ float t[32][33];
    int n0 = blockIdx.x * 32, k0 = blockIdx.y * 32;
    int tx = threadIdx.x, ty = threadIdx.y;   // 32 x 8
    #pragma unroll
    for (int i = 0; i < 32; i += 8)
        t[ty + i][tx] = W[(size_t)(k0 + ty + i) * N + n0 + tx];
    __syncthreads();
    #pragma unroll
    for (int i = 0; i < 32; i += 8) {
        float v = t[tx][ty + i];
        __nv_bfloat16 h = __float2bfloat16_rn(v);
        float rem = v - __bfloat162float(h);
        hi[(size_t)(n0 + ty + i) * K + k0 + tx] = h;
        lo[(size_t)(n0 + ty + i) * K + k0 + tx] = __float2bfloat16_rn(rem);
    }
}

// x split: fp32 -> bf16 hi/lo (elementwise, float4 granularity)
__global__ void xsplit_kernel(const float* __restrict__ x,
                              __nv_bfloat16* __restrict__ hi,
                              __nv_bfloat16* __restrict__ lo)
{
    int i = blockIdx.x * blockDim.x + threadIdx.x;
    if (i < BATCH * DIM / 4) {
        float4 v = reinterpret_cast<const float4*>(x)[i];
        uint2 hp, lp;
        hp.x = pack_bf2(v.x, v.y); hp.y = pack_bf2(v.z, v.w);
        lp.x = pack_bf2(v.x - bf_hi(v.x), v.y - bf_hi(v.y));
        lp.y = pack_bf2(v.z - bf_hi(v.z), v.w - bf_hi(v.w));
        reinterpret_cast<uint2*>(hi)[i] = hp;
        reinterpret_cast<uint2*>(lo)[i] = lp;
    }
}

// ---------------------------------------------------------------------------
// mma.sync GEMM: C[M,N] = epi(A @ Bt^T [+bias]).
//   A  : bf16 hi/lo [M,K] row-major (pre-split)
//   Bt : bf16 hi/lo [N,K] row-major (pre-split)
// PASSES=3: hi*hi + hi*lo + lo*hi (error compensated); PASSES=1: hi*hi only.
// Block tile 128x128, BK=32, 8 warps (4m x 2n), 3-stage cp.async pipeline.
// EPI bits: 1=tanh, 2=bias, 4=write fp32 Cf, 8=write hi/lo split, 16=write hi
// ---------------------------------------------------------------------------
#define BKT 32

template <int PASSES, int EPI>
__global__ __launch_bounds__(256, 2) void tgemm(
    int N, int K,
    const __nv_bfloat16* __restrict__ Ahi,
    const __nv_bfloat16* __restrict__ Alo,
    const __nv_bfloat16* __restrict__ Bhi,
    const __nv_bfloat16* __restrict__ Blo,
    const float* __restrict__ bias,
    float* __restrict__ Cf,
    __nv_bfloat16* __restrict__ Chi,
    __nv_bfloat16* __restrict__ Clo)
{
    constexpr int S_AHI = 0;
    constexpr int S_ALO = 8192;                            // 3-pass only
    constexpr int S_BHI = (PASSES == 3) ? 16384 : 8192;
    constexpr int S_BLO = 24576;                           // 3-pass only
    constexpr int STG   = (PASSES == 3) ? 32768 : 16384;

    extern __shared__ char smem[];
    const uint32_t sb = smem_u32(smem);
    const int tid = threadIdx.x, lane = tid & 31, wid = tid >> 5;
    const int wm = wid & 3, wn = wid >> 2;
    const int m0 = blockIdx.y * 128, n0 = blockIdx.x * 128;
    const int nk = K / BKT;

    const int t_row0 = tid >> 2, t_row1 = t_row0 + 64, t_kc = tid & 3;

    float acc[2][8][4];
    #pragma unroll
    for (int i = 0; i < 2; i++)
        #pragma unroll
        for (int j = 0; j < 8; j++)
            #pragma unroll
            for (int q = 0; q < 4; q++) acc[i][j][q] = 0.f;

    // issue async loads for k-chunk cs into stage cs%3
    auto issue = [&](int cs) {
        const uint32_t sbuf = sb + (uint32_t)(cs % 3) * STG;
        const int k0 = cs * BKT + t_kc * 8;
        #pragma unroll
        for (int t = 0; t < 2; t++) {
            const int row = t ? t_row1 : t_row0;
            const uint32_t off = sw_off(row, t_kc);
            cpa16(sbuf + S_AHI + off, Ahi + (size_t)(m0 + row) * K + k0);
            cpa16(sbuf + S_BHI + off, Bhi + (size_t)(n0 + row) * K + k0);
            if (PASSES == 3) {
                cpa16(sbuf + S_ALO + off, Alo + (size_t)(m0 + row) * K + k0);
                cpa16(sbuf + S_BLO + off, Blo + (size_t)(n0 + row) * K + k0);
            }
        }
        CP_COMMIT();
    };

    issue(0);
    issue(1);

    for (int c = 0; c < nk; c++) {
        if (c + 2 < nk) { CP_WAIT(1); } else { CP_WAIT(0); }
        __syncthreads();
        if (c + 2 < nk) issue(c + 2);

        const uint32_t sbase = sb + (uint32_t)(c % 3) * STG;
        #pragma unroll
        for (int k16 = 0; k16 < 2; k16++) {
            uint32_t ah[2][4], al[2][4];
            #pragma unroll
            for (int mt = 0; mt < 2; mt++) {
                int r  = wm * 32 + mt * 16 + (lane & 15);
                int kc = k16 * 2 + (lane >> 4);
                uint32_t off = sw_off(r, kc);
                ldsm4(ah[mt], sbase + S_AHI + off);
                if (PASSES == 3) ldsm4(al[mt], sbase + S_ALO + off);
            }
            #pragma unroll
            for (int g = 0; g < 4; g++) {
                int r  = wn * 64 + g * 16 + ((lane >> 4) << 3) + (lane & 7);
                int kc = k16 * 2 + ((lane >> 3) & 1);
                uint32_t off = sw_off(r, kc);
                uint32_t bh[4], bl[4];
                ldsm4(bh, sbase + S_BHI + off);
                if (PASSES == 3) ldsm4(bl, sbase + S_BLO + off);
                #pragma unroll
                for (int mt = 0; mt < 2; mt++) {
                    #pragma unroll
                    for (int h = 0; h < 2; h++) {
                        float* cc = acc[mt][g * 2 + h];
                        mma_bf16(cc, ah[mt], bh + h * 2);
                        if (PASSES == 3) {
                            mma_bf16(cc, ah[mt], bl + h * 2);
                            mma_bf16(cc, al[mt], bh + h * 2);
                        }
                    }
                }
            }
        }
        __syncthreads();
    }

    // epilogue
    #pragma unroll
    for (int mt = 0; mt < 2; mt++) {
        #pragma unroll
        for (int nt = 0; nt < 8; nt++) {
            int row = m0 + wm * 32 + mt * 16 + (lane >> 2);
            int col = n0 + wn * 64 + nt * 8 + (lane & 3) * 2;
            float b0 = 0.f, b1 = 0.f;
            if (EPI & 2) { b0 = __ldg(bias + col); b1 = __ldg(bias + col + 1); }
            float v0 = acc[mt][nt][0] + b0, v1 = acc[mt][nt][1] + b1;
            float v2 = acc[mt][nt][2] + b0, v3 = acc[mt][nt][3] + b1;
            if (EPI & 1) { v0 = tanhf(v0); v1 = tanhf(v1); v2 = tanhf(v2); v3 = tanhf(v3); }
            size_t o0 = (size_t)row * N + col;
            size_t o1 = (size_t)(row + 8) * N + col;
            if (EPI & 4) {
                *reinterpret_cast<float2*>(Cf + o0) = make_float2(v0, v1);
                *reinterpret_cast<float2*>(Cf + o1) = make_float2(v2, v3);
            }
            if (EPI & (8 | 16)) {
                *reinterpret_cast<uint32_t*>(Chi + o0) = pack_bf2(v0, v1);
                *reinterpret_cast<uint32_t*>(Chi + o1) = pack_bf2(v2, v3);
            }
            if (EPI & 8) {
                *reinterpret_cast<uint32_t*>(Clo + o0) =
                    pack_bf2(v0 - bf_hi(v0), v1 - bf_hi(v1));
                *reinterpret_cast<uint32_t*>(Clo + o1) =
                    pack_bf2(v2 - bf_hi(v2), v3 - bf_hi(v3));
            }
        }
    }
}

// ---------------------------------------------------------------------------
// Row reductions + Newton rootfind + output scale
// ---------------------------------------------------------------------------
__device__ __forceinline__ float warpsum(float v) {
    #pragma unroll
    for (int o = 16; o > 0; o >>= 1) v += __shfl_down_sync(0xFFFFFFFFu, v, o);
    return v;
}

__global__ void reduce_kernel(const float* __restrict__ x)
{
    int wid = threadIdx.x >> 5, lane = threadIdx.x & 31;
    int row = blockIdx.x * 8 + wid;
    float sy = 0.f, sx = 0.f, sf = 0.f;
    const float* yr = g_Yx + (size_t)row * VO;
    const float* xr = x    + (size_t)row * DIM;
    const float* fr = g_FH + (size_t)row * DIM;
    for (int j = lane; j < VO; j += 32) { float v = yr[j]; sy += v * v; }
    for (int d = lane; d < DIM; d += 32) {
        float v = xr[d]; sx += v * v;
        float f = fr[d]; sf += f * f;
    }
    sy = warpsum(sy); sx = warpsum(sx); sf = warpsum(sf);
    if (lane == 0) {
        g_tgt[row] = 0.99f * (sy + 0.01f * sx);
        g_s[row]   = sf;
    }
}

#define NG 8
__global__ __launch_bounds__(256) void newton_kernel(const float* __restrict__ Wv2)
{
    __shared__ float sh_h[NG][HV];
    __shared__ float sh_u[NG][HV];
    __shared__ float sh_part[8][NG];
    __shared__ float sh_alpha[NG], sh_resid[NG], sh_s[NG], sh_tgt[NG];
    __shared__ int   sh_active[NG], sh_upd[NG], sh_any;

    const int tid  = threadIdx.x;
    const int lane = tid & 31, wid = tid >> 5;
    const int base = blockIdx.x * NG;

    for (int idx = tid; idx < NG * (HV / 4); idx += 256) {
        int sI = idx >> 7, v = idx & 127;
        reinterpret_cast<float4*>(sh_u[sI])[v] =
            reinterpret_cast<const float4*>(g_U + (size_t)(base + sI) * HV)[v];
    }
    if (tid < NG) {
        sh_alpha[tid]  = 1.0f;
        sh_active[tid] = 1;
        sh_s[tid]   = g_s[base + tid];
        sh_tgt[tid] = g_tgt[base + tid];
    }
    __syncthreads();

    for (int it = 0; it < 50; it++) {
        for (int idx = tid; idx < NG * HV; idx += 256) {
            int sI = idx >> 9, k = idx & (HV - 1);
            if (sh_active[sI]) sh_h[sI][k] = tanhf(sh_alpha[sI] * sh_u[sI][k]);
        }
        __syncthreads();

        float accY[NG];
        #pragma unroll
        for (int s2 = 0; s2 < NG; s2++) accY[s2] = 0.f;
        const int j = tid;
        for (int k = 0; k < HV; k += 4) {
            float w0 = Wv2[(k + 0) * VO + j];
            float w1 = Wv2[(k + 1) * VO + j];
            float w2 = Wv2[(k + 2) * VO + j];
            float w3 = Wv2[(k + 3) * VO + j];
            #pragma unroll
            for (int s2 = 0; s2 < NG; s2++) {
                float4 hv = *reinterpret_cast<const float4*>(&sh_h[s2][k]);
                accY[s2] += hv.x * w0 + hv.y * w1 + hv.z * w2 + hv.w * w3;
            }
        }
        #pragma unroll
        for (int s2 = 0; s2 < NG; s2++) {
            float v = warpsum(accY[s2] * accY[s2]);
            if (lane == 0) sh_part[wid][s2] = v;
        }
        __syncthreads();
        if (tid < NG) {
            sh_upd[tid] = 0;
            if (sh_active[tid]) {
                float Vz = 0.f;
                #pragma unroll
                for (int w = 0; w < 8; w++) Vz += sh_part[w][tid];
                float a = sh_alpha[tid];
                Vz += 0.01f * a * a * sh_s[tid];
                float resid = Vz - sh_tgt[tid];
                if (resid > 1e-3f) { sh_upd[tid] = 1; sh_resid[tid] = resid; }
                else               sh_active[tid] = 0;
            }
        }
        __syncthreads();
        if (tid == 0) {
            int a = 0;
            #pragma unroll
            for (int s2 = 0; s2 < NG; s2++) a |= sh_upd[s2];
            sh_any = a;
        }
        __syncthreads();
        if (!sh_any) break;

        float accW[NG];
        #pragma unroll
        for (int s2 = 0; s2 < NG; s2++) accW[s2] = 0.f;
        for (int k = 0; k < HV; k += 4) {
            float w0 = Wv2[(k + 0) * VO + j];
            float w1 = Wv2[(k + 1) * VO + j];
            float w2 = Wv2[(k + 2) * VO + j];
            float w3 = Wv2[(k + 3) * VO + j];
            #pragma unroll
            for (int s2 = 0; s2 < NG; s2++) {
                float4 hv = *reinterpret_cast<const float4*>(&sh_h[s2][k]);
                float4 uv = *reinterpret_cast<const float4*>(&sh_u[s2][k]);
                accW[s2] += (1.f - hv.x * hv.x) * uv.x * w0
                          + (1.f - hv.y * hv.y) * uv.y * w1
                          + (1.f - hv.z * hv.z) * uv.z * w2
                          + (1.f - hv.w * hv.w) * uv.w * w3;
            }
        }
        #pragma unroll
        for (int s2 = 0; s2 < NG; s2++) {
            float v = warpsum(accY[s2] * accW[s2]);
            if (lane == 0) sh_part[wid][s2] = v;
        }
        __syncthreads();
        if (tid < NG && sh_upd[tid]) {
            float dot = 0.f;
            #pragma unroll
            for (int w = 0; w < 8; w++) dot += sh_part[w][tid];
            float a   = sh_alpha[tid];
            float dVda = 2.f * dot + 0.02f * a * sh_s[tid];
            sh_alpha[tid] = a - sh_resid[tid] / dVda;
        }
        __syncthreads();
    }

    if (tid < NG) g_alpha[base + tid] = sh_alpha[tid];
}

__global__ void scale_out_kernel(float* __restrict__ out)
{
    int i = blockIdx.x * blockDim.x + threadIdx.x;
    const int total4 = BATCH * (DIM / 4);
    if (i < total4) {
        float a = g_alpha[i >> 7];
        float4 v = reinterpret_cast<const float4*>(g_FH)[i];
        v.x *= a; v.y *= a; v.z *= a; v.w *= a;
        reinterpret_cast<float4*>(out)[i] = v;
    }
}

// ---------------------------------------------------------------------------
extern "C" void kernel_launch(void* const* d_in, const int* in_sizes, int n_in,
                              void* d_out, int out_size)
{
    const float* x   = (const float*)d_in[0];
    const float* W1  = (const float*)d_in[1];
    const float* b1  = (const float*)d_in[2];
    const float* W2  = (const float*)d_in[3];
    const float* b2  = (const float*)d_in[4];
    const float* Wv1 = (const float*)d_in[5];
    const float* Wv2 = (const float*)d_in[6];
    float* out = (float*)d_out;

    float* FH = 0;  cudaGetSymbolAddress((void**)&FH, g_FH);
    float* Yx = 0;  cudaGetSymbolAddress((void**)&Yx, g_Yx);
    float* U  = 0;  cudaGetSymbolAddress((void**)&U,  g_U);
    __nv_bfloat16* xhi  = 0; cudaGetSymbolAddress((void**)&xhi,  g_xhi);
    __nv_bfloat16* xlo  = 0; cudaGetSymbolAddress((void**)&xlo,  g_xlo);
    __nv_bfloat16* H1hi = 0; cudaGetSymbolAddress((void**)&H1hi, g_H1hi);
    __nv_bfloat16* H1lo = 0; cudaGetSymbolAddress((void**)&H1lo, g_H1lo);
    __nv_bfloat16* FHhi = 0; cudaGetSymbolAddress((void**)&FHhi, g_FHhi);
    __nv_bfloat16* FHlo = 0; cudaGetSymbolAddress((void**)&FHlo, g_FHlo);
    __nv_bfloat16* HXhi = 0; cudaGetSymbolAddress((void**)&HXhi, g_HXhi);
    __nv_bfloat16* W1h = 0; cudaGetSymbolAddress((void**)&W1h, g_W1t_hi);
    __nv_bfloat16* W1l = 0; cudaGetSymbolAddress((void**)&W1l, g_W1t_lo);
    __nv_bfloat16* W2h = 0; cudaGetSymbolAddress((void**)&W2h, g_W2t_hi);
    __nv_bfloat16* W2l = 0; cudaGetSymbolAddress((void**)&W2l, g_W2t_lo);
    __nv_bfloat16* V1h = 0; cudaGetSymbolAddress((void**)&V1h, g_Wv1t_hi);
    __nv_bfloat16* V1l = 0; cudaGetSymbolAddress((void**)&V1l, g_Wv1t_lo);
    __nv_bfloat16* V2h = 0; cudaGetSymbolAddress((void**)&V2h, g_Wv2t_hi);
    __nv_bfloat16* V2l = 0; cudaGetSymbolAddress((void**)&V2l, g_Wv2t_lo);

    cudaFuncSetAttribute(tgemm<3,11>, cudaFuncAttributeMaxDynamicSharedMemorySize, 98304);
    cudaFuncSetAttribute(tgemm<3,14>, cudaFuncAttributeMaxDynamicSharedMemorySize, 98304);
    cudaFuncSetAttribute(tgemm<1,17>, cudaFuncAttributeMaxDynamicSharedMemorySize, 49152);
    cudaFuncSetAttribute(tgemm<1,4>,  cudaFuncAttributeMaxDynamicSharedMemorySize, 49152);

    dim3 tb(32, 8);
    // weight transpose + split
    tsplit_kernel<<<dim3(HID / 32, DIM / 32), tb>>>(W1,  DIM, HID, W1h, W1l);
    tsplit_kernel<<<dim3(DIM / 32, HID / 32), tb>>>(W2,  HID, DIM, W2h, W2l);
    tsplit_kernel<<<dim3(HV  / 32, DIM / 32), tb>>>(Wv1, DIM, HV,  V1h, V1l);
    tsplit_kernel<<<dim3(VO  / 32, HV  / 32), tb>>>(Wv2, HV,  VO,  V2h, V2l);
    // x split
    xsplit_kernel<<<(BATCH * DIM / 4 + 255) / 256, 256>>>(x, xhi, xlo);

    // GEMM1: H1(hi/lo) = tanh(x@W1 + b1)   [3-pass, tanh+bias+split]
    tgemm<3, 1|2|8><<<dim3(HID / 128, BATCH / 128), 256, 98304>>>(
        HID, DIM, xhi, xlo, W1h, W1l, b1, 0, H1hi, H1lo);
    // GEMM2: FH(f32 + hi/lo) = H1@W2 + b2  [3-pass, bias+fp32+split]
    tgemm<3, 2|4|8><<<dim3(DIM / 128, BATCH / 128), 256, 98304>>>(
        DIM, HID, H1hi, H1lo, W2h, W2l, b2, FH, FHhi, FHlo);
    // GEMM3: HX(hi) = tanh(x@Wv1)          [1-pass, tanh + hi-only]
    tgemm<1, 1|16><<<dim3(HV / 128, BATCH / 128), 256, 49152>>>(
        HV, DIM, xhi, 0, V1h, 0, 0, 0, HXhi, 0);
    // GEMM4: Yx = HX@Wv2                   [1-pass, fp32]
    tgemm<1, 4><<<dim3(VO / 128, BATCH / 128), 256, 49152>>>(
        VO, HV, HXhi, 0, V2h, 0, 0, Yx, 0, 0);
    // GEMM5: U = FH@Wv1                    [1-pass, fp32]
    tgemm<1, 4><<<dim3(HV / 128, BATCH / 128), 256, 49152>>>(
        HV, DIM, FHhi, 0, V1h, 0, 0, U, 0, 0);

    reduce_kernel<<<BATCH / 8, 256>>>(x);
    newton_kernel<<<BATCH / NG, 256>>>(Wv2);
    scale_out_kernel<<<(BATCH * (DIM / 4) + 255) / 256, 256>>>(out);
}

// round 6
// speedup vs baseline: 3.5320x; 1.2790x over previous
#include <cuda_runtime.h>
#include <cuda_bf16.h>
#include <stdint.h>
#include <math.h>

// Problem constants
#define BATCH 8192
#define DIM   512
#define HID   2048
#define HV    512
#define VO    256

// ---------------------------------------------------------------------------
// Device-global scratch (no cudaMalloc allowed)
// ---------------------------------------------------------------------------
__device__ __align__(256) float g_FH[BATCH * DIM];      // fhatx fp32
__device__ __align__(256) float g_Yx[BATCH * VO];
__device__ __align__(256) float g_Y1[BATCH * VO];       // tanh(U)@Wv2 (bf16 approx)
__device__ __align__(256) float g_U [BATCH * HV];
__device__ __align__(256) float g_tgt[BATCH];
__device__ __align__(256) float g_s  [BATCH];
__device__ __align__(256) float g_resid[BATCH];
__device__ __align__(256) float g_alpha[BATCH];

// activations, bf16 hi/lo
__device__ __align__(256) __nv_bfloat16 g_xhi[BATCH * DIM];
__device__ __align__(256) __nv_bfloat16 g_xlo[BATCH * DIM];
__device__ __align__(256) __nv_bfloat16 g_H1hi[BATCH * HID];
__device__ __align__(256) __nv_bfloat16 g_H1lo[BATCH * HID];
__device__ __align__(256) __nv_bfloat16 g_FHhi[BATCH * DIM];
__device__ __align__(256) __nv_bfloat16 g_FHlo[BATCH * DIM];
__device__ __align__(256) __nv_bfloat16 g_HXhi[BATCH * HV];
__device__ __align__(256) __nv_bfloat16 g_Thi [BATCH * HV];   // tanh(U) bf16

// weights: transposed to [N,K] + split into bf16 hi/lo
__device__ __align__(256) __nv_bfloat16 g_W1t_hi[HID * DIM];
__device__ __align__(256) __nv_bfloat16 g_W1t_lo[HID * DIM];
__device__ __align__(256) __nv_bfloat16 g_W2t_hi[DIM * HID];
__device__ __align__(256) __nv_bfloat16 g_W2t_lo[DIM * HID];
__device__ __align__(256) __nv_bfloat16 g_Wv1t_hi[HV * DIM];
__device__ __align__(256) __nv_bfloat16 g_Wv1t_lo[HV * DIM];
__device__ __align__(256) __nv_bfloat16 g_Wv2t_hi[VO * HV];

// ---------------------------------------------------------------------------
// Helpers
// ---------------------------------------------------------------------------
__device__ __forceinline__ uint32_t smem_u32(const void* p) {
    uint32_t a;
    asm("{ .reg .u64 t; cvta.to.shared.u64 t, %1; cvt.u32.u64 %0, t; }"
        : "=r"(a) : "l"(p));
    return a;
}
__device__ __forceinline__ void ldsm4(uint32_t* r, uint32_t addr) {
    asm volatile("ldmatrix.sync.aligned.m8n8.x4.shared.b16 {%0,%1,%2,%3}, [%4];"
                 : "=r"(r[0]), "=r"(r[1]), "=r"(r[2]), "=r"(r[3]) : "r"(addr));
}
__device__ __forceinline__ void mma_bf16(float* c, const uint32_t* a, const uint32_t* b) {
    asm volatile("mma.sync.aligned.m16n8k16.row.col.f32.bf16.bf16.f32 "
                 "{%0,%1,%2,%3}, {%4,%5,%6,%7}, {%8,%9}, {%0,%1,%2,%3};"
                 : "+f"(c[0]), "+f"(c[1]), "+f"(c[2]), "+f"(c[3])
                 : "r"(a[0]), "r"(a[1]), "r"(a[2]), "r"(a[3]),
                   "r"(b[0]), "r"(b[1]));
}
__device__ __forceinline__ void cpa16(uint32_t dst, const void* src) {
    asm volatile("cp.async.cg.shared.global [%0], [%1], 16;" :: "r"(dst), "l"(src));
}
#define CP_COMMIT() asm volatile("cp.async.commit_group;" ::: "memory")
#define CP_WAIT(n)  asm volatile("cp.async.wait_group %0;" :: "n"(n) : "memory")

// SMEM swizzle for 64-byte rows (32 bf16): chunk = 16B unit
__device__ __forceinline__ uint32_t sw_off(int row, int kc) {
    return (uint32_t)(row * 64 + (((kc) ^ ((row >> 1) & 3)) << 4));
}
__device__ __forceinline__ uint32_t pack_bf2(float a, float b) {
    __nv_bfloat162 h = __floats2bfloat162_rn(a, b);
    return *reinterpret_cast<uint32_t*>(&h);
}
__device__ __forceinline__ float bf_hi(float v) {
    return __bfloat162float(__float2bfloat16_rn(v));
}

// ---------------------------------------------------------------------------
// Weight transpose + hi/lo split: W[K,N] row-major -> hi/lo[N,K]
// ---------------------------------------------------------------------------
__global__ void tsplit_kernel(const float* __restrict__ W, int K, int N,
                              __nv_bfloat16* __restrict__ hi,
                              __nv_bfloat16* __restrict__ lo)
{
    __shared__ float t[32][33];
    int n0 = blockIdx.x * 32, k0 = blockIdx.y * 32;
    int tx = threadIdx.x, ty = threadIdx.y;   // 32 x 8
    #pragma unroll
    for (int i = 0; i < 32; i += 8)
        t[ty + i][tx] = W[(size_t)(k0 + ty + i) * N + n0 + tx];
    __syncthreads();
    #pragma unroll
    for (int i = 0; i < 32; i += 8) {
        float v = t[tx][ty + i];
        __nv_bfloat16 h = __float2bfloat16_rn(v);
        hi[(size_t)(n0 + ty + i) * K + k0 + tx] = h;
        if (lo) {
            float rem = v - __bfloat162float(h);
            lo[(size_t)(n0 + ty + i) * K + k0 + tx] = __float2bfloat16_rn(rem);
        }
    }
}

// x split: fp32 -> bf16 hi/lo
__global__ void xsplit_kernel(const float* __restrict__ x,
                              __nv_bfloat16* __restrict__ hi,
                              __nv_bfloat16* __restrict__ lo)
{
    int i = blockIdx.x * blockDim.x + threadIdx.x;
    if (i < BATCH * DIM / 4) {
        float4 v = reinterpret_cast<const float4*>(x)[i];
        uint2 hp, lp;
        hp.x = pack_bf2(v.x, v.y); hp.y = pack_bf2(v.z, v.w);
        lp.x = pack_bf2(v.x - bf_hi(v.x), v.y - bf_hi(v.y));
        lp.y = pack_bf2(v.z - bf_hi(v.z), v.w - bf_hi(v.w));
        reinterpret_cast<uint2*>(hi)[i] = hp;
        reinterpret_cast<uint2*>(lo)[i] = lp;
    }
}

// ---------------------------------------------------------------------------
// mma.sync GEMM: C[M,N] = epi(A @ Bt^T [+bias]).
// PASSES=3: hi*hi + hi*lo + lo*hi (error compensated); PASSES=1: hi*hi only.
// Block 128x128, BK=32, 8 warps (4m x 2n), multi-stage cp.async pipeline,
// ONE __syncthreads per chunk.
// EPI bits: 1=tanh->all, 2=bias, 4=write fp32 Cf, 8=write hi/lo split,
//           16=write hi only, 32=write tanh(v) to Chi (Cf gets raw v)
// ---------------------------------------------------------------------------
#define BKT 32

template <int PASSES, int EPI>
__global__ __launch_bounds__(256, 2) void tgemm(
    int N, int K,
    const __nv_bfloat16* __restrict__ Ahi,
    const __nv_bfloat16* __restrict__ Alo,
    const __nv_bfloat16* __restrict__ Bhi,
    const __nv_bfloat16* __restrict__ Blo,
    const float* __restrict__ bias,
    float* __restrict__ Cf,
    __nv_bfloat16* __restrict__ Chi,
    __nv_bfloat16* __restrict__ Clo)
{
    constexpr int S_AHI = 0;
    constexpr int S_ALO = 8192;                            // 3-pass only
    constexpr int S_BHI = (PASSES == 3) ? 16384 : 8192;
    constexpr int S_BLO = 24576;                           // 3-pass only
    constexpr int STG   = (PASSES == 3) ? 32768 : 16384;
    constexpr int NSTG  = (PASSES == 3) ? 3 : 4;

    extern __shared__ char smem[];
    const uint32_t sb = smem_u32(smem);
    const int tid = threadIdx.x, lane = tid & 31, wid = tid >> 5;
    const int wm = wid & 3, wn = wid >> 2;
    const int m0 = blockIdx.y * 128, n0 = blockIdx.x * 128;
    const int nk = K / BKT;

    const int t_row0 = tid >> 2, t_row1 = t_row0 + 64, t_kc = tid & 3;

    float acc[2][8][4];
    #pragma unroll
    for (int i = 0; i < 2; i++)
        #pragma unroll
        for (int j = 0; j < 8; j++)
            #pragma unroll
            for (int q = 0; q < 4; q++) acc[i][j][q] = 0.f;

    auto issue = [&](int cs) {
        const uint32_t sbuf = sb + (uint32_t)(cs % NSTG) * STG;
        const int k0 = cs * BKT + t_kc * 8;
        #pragma unroll
        for (int t = 0; t < 2; t++) {
            const int row = t ? t_row1 : t_row0;
            const uint32_t off = sw_off(row, t_kc);
            cpa16(sbuf + S_AHI + off, Ahi + (size_t)(m0 + row) * K + k0);
            cpa16(sbuf + S_BHI + off, Bhi + (size_t)(n0 + row) * K + k0);
            if (PASSES == 3) {
                cpa16(sbuf + S_ALO + off, Alo + (size_t)(m0 + row) * K + k0);
                cpa16(sbuf + S_BLO + off, Blo + (size_t)(n0 + row) * K + k0);
            }
        }
        CP_COMMIT();
    };

    #pragma unroll
    for (int p = 0; p < NSTG - 1; p++) issue(p);

    for (int c = 0; c < nk; c++) {
        if (c + NSTG - 1 < nk) { CP_WAIT(NSTG - 2); } else { CP_WAIT(0); }
        __syncthreads();
        if (c + NSTG - 1 < nk) issue(c + NSTG - 1);

        const uint32_t sbase = sb + (uint32_t)(c % NSTG) * STG;
        #pragma unroll
        for (int k16 = 0; k16 < 2; k16++) {
            uint32_t ah[2][4], al[2][4];
            #pragma unroll
            for (int mt = 0; mt < 2; mt++) {
                int r  = wm * 32 + mt * 16 + (lane & 15);
                int kc = k16 * 2 + (lane >> 4);
                uint32_t off = sw_off(r, kc);
                ldsm4(ah[mt], sbase + S_AHI + off);
                if (PASSES == 3) ldsm4(al[mt], sbase + S_ALO + off);
            }
            #pragma unroll
            for (int g = 0; g < 4; g++) {
                int r  = wn * 64 + g * 16 + ((lane >> 4) << 3) + (lane & 7);
                int kc = k16 * 2 + ((lane >> 3) & 1);
                uint32_t off = sw_off(r, kc);
                uint32_t bh[4], bl[4];
                ldsm4(bh, sbase + S_BHI + off);
                if (PASSES == 3) ldsm4(bl, sbase + S_BLO + off);
                #pragma unroll
                for (int mt = 0; mt < 2; mt++) {
                    #pragma unroll
                    for (int h = 0; h < 2; h++) {
                        float* cc = acc[mt][g * 2 + h];
                        mma_bf16(cc, ah[mt], bh + h * 2);
                        if (PASSES == 3) {
                            mma_bf16(cc, ah[mt], bl + h * 2);
                            mma_bf16(cc, al[mt], bh + h * 2);
                        }
                    }
                }
            }
        }
        // NOTE: no trailing __syncthreads — the top barrier of the next
        // iteration orders stage reuse (issue(c+NSTG-1) overwrites the stage
        // last read at iteration c-1, which all warps finished before that
        // barrier).
    }

    // epilogue
    #pragma unroll
    for (int mt = 0; mt < 2; mt++) {
        #pragma unroll
        for (int nt = 0; nt < 8; nt++) {
            int row = m0 + wm * 32 + mt * 16 + (lane >> 2);
            int col = n0 + wn * 64 + nt * 8 + (lane & 3) * 2;
            float b0 = 0.f, b1 = 0.f;
            if (EPI & 2) { b0 = __ldg(bias + col); b1 = __ldg(bias + col + 1); }
            float v0 = acc[mt][nt][0] + b0, v1 = acc[mt][nt][1] + b1;
            float v2 = acc[mt][nt][2] + b0, v3 = acc[mt][nt][3] + b1;
            if (EPI & 1) { v0 = tanhf(v0); v1 = tanhf(v1); v2 = tanhf(v2); v3 = tanhf(v3); }
            size_t o0 = (size_t)row * N + col;
            size_t o1 = (size_t)(row + 8) * N + col;
            if (EPI & 4) {
                *reinterpret_cast<float2*>(Cf + o0) = make_float2(v0, v1);
                *reinterpret_cast<float2*>(Cf + o1) = make_float2(v2, v3);
            }
            if (EPI & 32) {
                *reinterpret_cast<uint32_t*>(Chi + o0) = pack_bf2(tanhf(v0), tanhf(v1));
                *reinterpret_cast<uint32_t*>(Chi + o1) = pack_bf2(tanhf(v2), tanhf(v3));
            } else if (EPI & (8 | 16)) {
                *reinterpret_cast<uint32_t*>(Chi + o0) = pack_bf2(v0, v1);
                *reinterpret_cast<uint32_t*>(Chi + o1) = pack_bf2(v2, v3);
            }
            if (EPI & 8) {
                *reinterpret_cast<uint32_t*>(Clo + o0) =
                    pack_bf2(v0 - bf_hi(v0), v1 - bf_hi(v1));
                *reinterpret_cast<uint32_t*>(Clo + o1) =
                    pack_bf2(v2 - bf_hi(v2), v3 - bf_hi(v3));
            }
        }
    }
}

// ---------------------------------------------------------------------------
// Row reductions:
//   tgt  = 0.99*(||Yx||^2 + 0.01*||x||^2)
//   s    = ||FH||^2
//   resid(alpha=1) = ||Y1||^2 + 0.01*s - tgt
// ---------------------------------------------------------------------------
__device__ __forceinline__ float warpsum(float v) {
    #pragma unroll
    for (int o = 16; o > 0; o >>= 1) v += __shfl_down_sync(0xFFFFFFFFu, v, o);
    return v;
}

__global__ void reduce_kernel(const float* __restrict__ x)
{
    int wid = threadIdx.x >> 5, lane = threadIdx.x & 31;
    int row = blockIdx.x * 8 + wid;
    float sy = 0.f, s1 = 0.f, sx = 0.f, sf = 0.f;
    const float* yr = g_Yx + (size_t)row * VO;
    const float* y1 = g_Y1 + (size_t)row * VO;
    const float* xr = x    + (size_t)row * DIM;
    const float* fr = g_FH + (size_t)row * DIM;
    for (int j = lane; j < VO; j += 32) {
        float v = yr[j]; sy += v * v;
        float w = y1[j]; s1 += w * w;
    }
    for (int d = lane; d < DIM; d += 32) {
        float v = xr[d]; sx += v * v;
        float f = fr[d]; sf += f * f;
    }
    sy = warpsum(sy); s1 = warpsum(s1); sx = warpsum(sx); sf = warpsum(sf);
    if (lane == 0) {
        float tgt = 0.99f * (sy + 0.01f * sx);
        g_tgt[row]   = tgt;
        g_s[row]     = sf;
        g_resid[row] = (s1 + 0.01f * sf) - tgt;
    }
}

// ---------------------------------------------------------------------------
// Newton rootfind with precomputed alpha=1 residual fast path.
// Blocks whose samples all satisfy resid<=TOL exit immediately.
// Stragglers run the exact fp32 masked Newton loop (recomputes resid exactly).
// ---------------------------------------------------------------------------
#define NG 8
__global__ __launch_bounds__(256) void newton_kernel(const float* __restrict__ Wv2)
{
    __shared__ float sh_h[NG][HV];
    __shared__ float sh_u[NG][HV];
    __shared__ float sh_part[8][NG];
    __shared__ float sh_alpha[NG], sh_resid[NG], sh_s[NG], sh_tgt[NG];
    __shared__ int   sh_active[NG], sh_upd[NG], sh_any;

    const int tid  = threadIdx.x;
    const int lane = tid & 31, wid = tid >> 5;
    const int base = blockIdx.x * NG;

    // fast path: precomputed residual at alpha = 1
    if (tid < NG) {
        sh_active[tid] = (g_resid[base + tid] > 1e-3f) ? 1 : 0;
        sh_alpha[tid]  = 1.0f;
    }
    if (tid == 0) {
        int a = 0;
        #pragma unroll
        for (int s2 = 0; s2 < NG; s2++) a |= ((g_resid[base + s2] > 1e-3f) ? 1 : 0);
        sh_any = a;
    }
    __syncthreads();
    if (!sh_any) {
        if (tid < NG) g_alpha[base + tid] = 1.0f;
        return;
    }

    // slow path (exact fp32), masked per sample
    for (int idx = tid; idx < NG * (HV / 4); idx += 256) {
        int sI = idx >> 7, v = idx & 127;
        reinterpret_cast<float4*>(sh_u[sI])[v] =
            reinterpret_cast<const float4*>(g_U + (size_t)(base + sI) * HV)[v];
    }
    if (tid < NG) {
        sh_s[tid]   = g_s[base + tid];
        sh_tgt[tid] = g_tgt[base + tid];
    }
    __syncthreads();

    for (int it = 0; it < 50; it++) {
        for (int idx = tid; idx < NG * HV; idx += 256) {
            int sI = idx >> 9, k = idx & (HV - 1);
            if (sh_active[sI]) sh_h[sI][k] = tanhf(sh_alpha[sI] * sh_u[sI][k]);
        }
        __syncthreads();

        float accY[NG];
        #pragma unroll
        for (int s2 = 0; s2 < NG; s2++) accY[s2] = 0.f;
        const int j = tid;
        for (int k = 0; k < HV; k += 4) {
            float w0 = Wv2[(k + 0) * VO + j];
            float w1 = Wv2[(k + 1) * VO + j];
            float w2 = Wv2[(k + 2) * VO + j];
            float w3 = Wv2[(k + 3) * VO + j];
            #pragma unroll
            for (int s2 = 0; s2 < NG; s2++) {
                float4 hv = *reinterpret_cast<const float4*>(&sh_h[s2][k]);
                accY[s2] += hv.x * w0 + hv.y * w1 + hv.z * w2 + hv.w * w3;
            }
        }
        #pragma unroll
        for (int s2 = 0; s2 < NG; s2++) {
            float v = warpsum(accY[s2] * accY[s2]);
            if (lane == 0) sh_part[wid][s2] = v;
        }
        __syncthreads();
        if (tid < NG) {
            sh_upd[tid] = 0;
            if (sh_active[tid]) {
                float Vz = 0.f;
                #pragma unroll
                for (int w = 0; w < 8; w++) Vz += sh_part[w][tid];
                float a = sh_alpha[tid];
                Vz += 0.01f * a * a * sh_s[tid];
                float resid = Vz - sh_tgt[tid];
                if (resid > 1e-3f) { sh_upd[tid] = 1; sh_resid[tid] = resid; }
                else               sh_active[tid] = 0;
            }
        }
        __syncthreads();
        if (tid == 0) {
            int a = 0;
            #pragma unroll
            for (int s2 = 0; s2 < NG; s2++) a |= sh_upd[s2];
            sh_any = a;
        }
        __syncthreads();
        if (!sh_any) break;

        float accW[NG];
        #pragma unroll
        for (int s2 = 0; s2 < NG; s2++) accW[s2] = 0.f;
        for (int k = 0; k < HV; k += 4) {
            float w0 = Wv2[(k + 0) * VO + j];
            float w1 = Wv2[(k + 1) * VO + j];
            float w2 = Wv2[(k + 2) * VO + j];
            float w3 = Wv2[(k + 3) * VO + j];
            #pragma unroll
            for (int s2 = 0; s2 < NG; s2++) {
                float4 hv = *reinterpret_cast<const float4*>(&sh_h[s2][k]);
                float4 uv = *reinterpret_cast<const float4*>(&sh_u[s2][k]);
                accW[s2] += (1.f - hv.x * hv.x) * uv.x * w0
                          + (1.f - hv.y * hv.y) * uv.y * w1
                          + (1.f - hv.z * hv.z) * uv.z * w2
                          + (1.f - hv.w * hv.w) * uv.w * w3;
            }
        }
        #pragma unroll
        for (int s2 = 0; s2 < NG; s2++) {
            float v = warpsum(accY[s2] * accW[s2]);
            if (lane == 0) sh_part[wid][s2] = v;
        }
        __syncthreads();
        if (tid < NG && sh_upd[tid]) {
            float dot = 0.f;
            #pragma unroll
            for (int w = 0; w < 8; w++) dot += sh_part[w][tid];
            float a   = sh_alpha[tid];
            float dVda = 2.f * dot + 0.02f * a * sh_s[tid];
            sh_alpha[tid] = a - sh_resid[tid] / dVda;
        }
        __syncthreads();
    }

    if (tid < NG) g_alpha[base + tid] = sh_alpha[tid];
}

__global__ void scale_out_kernel(float* __restrict__ out)
{
    int i = blockIdx.x * blockDim.x + threadIdx.x;
    const int total4 = BATCH * (DIM / 4);
    if (i < total4) {
        float a = g_alpha[i >> 7];
        float4 v = reinterpret_cast<const float4*>(g_FH)[i];
        v.x *= a; v.y *= a; v.z *= a; v.w *= a;
        reinterpret_cast<float4*>(out)[i] = v;
    }
}

// ---------------------------------------------------------------------------
extern "C" void kernel_launch(void* const* d_in, const int* in_sizes, int n_in,
                              void* d_out, int out_size)
{
    const float* x   = (const float*)d_in[0];
    const float* W1  = (const float*)d_in[1];
    const float* b1  = (const float*)d_in[2];
    const float* W2  = (const float*)d_in[3];
    const float* b2  = (const float*)d_in[4];
    const float* Wv1 = (const float*)d_in[5];
    const float* Wv2 = (const float*)d_in[6];
    float* out = (float*)d_out;

    float* FH = 0;  cudaGetSymbolAddress((void**)&FH, g_FH);
    float* Yx = 0;  cudaGetSymbolAddress((void**)&Yx, g_Yx);
    float* Y1 = 0;  cudaGetSymbolAddress((void**)&Y1, g_Y1);
    float* U  = 0;  cudaGetSymbolAddress((void**)&U,  g_U);
    __nv_bfloat16* xhi  = 0; cudaGetSymbolAddress((void**)&xhi,  g_xhi);
    __nv_bfloat16* xlo  = 0; cudaGetSymbolAddress((void**)&xlo,  g_xlo);
    __nv_bfloat16* H1hi = 0; cudaGetSymbolAddress((void**)&H1hi, g_H1hi);
    __nv_bfloat16* H1lo = 0; cudaGetSymbolAddress((void**)&H1lo, g_H1lo);
    __nv_bfloat16* FHhi = 0; cudaGetSymbolAddress((void**)&FHhi, g_FHhi);
    __nv_bfloat16* FHlo = 0; cudaGetSymbolAddress((void**)&FHlo, g_FHlo);
    __nv_bfloat16* HXhi = 0; cudaGetSymbolAddress((void**)&HXhi, g_HXhi);
    __nv_bfloat16* Thi  = 0; cudaGetSymbolAddress((void**)&Thi,  g_Thi);
    __nv_bfloat16* W1h = 0; cudaGetSymbolAddress((void**)&W1h, g_W1t_hi);
    __nv_bfloat16* W1l = 0; cudaGetSymbolAddress((void**)&W1l, g_W1t_lo);
    __nv_bfloat16* W2h = 0; cudaGetSymbolAddress((void**)&W2h, g_W2t_hi);
    __nv_bfloat16* W2l = 0; cudaGetSymbolAddress((void**)&W2l, g_W2t_lo);
    __nv_bfloat16* V1h = 0; cudaGetSymbolAddress((void**)&V1h, g_Wv1t_hi);
    __nv_bfloat16* V1l = 0; cudaGetSymbolAddress((void**)&V1l, g_Wv1t_lo);
    __nv_bfloat16* V2h = 0; cudaGetSymbolAddress((void**)&V2h, g_Wv2t_hi);

    cudaFuncSetAttribute(tgemm<3,11>, cudaFuncAttributeMaxDynamicSharedMemorySize, 98304);
    cudaFuncSetAttribute(tgemm<3,14>, cudaFuncAttributeMaxDynamicSharedMemorySize, 98304);
    cudaFuncSetAttribute(tgemm<1,17>, cudaFuncAttributeMaxDynamicSharedMemorySize, 65536);
    cudaFuncSetAttribute(tgemm<1,4>,  cudaFuncAttributeMaxDynamicSharedMemorySize, 65536);
    cudaFuncSetAttribute(tgemm<1,36>, cudaFuncAttributeMaxDynamicSharedMemorySize, 65536);

    dim3 tb(32, 8);
    // weight transpose + split
    tsplit_kernel<<<dim3(HID / 32, DIM / 32), tb>>>(W1,  DIM, HID, W1h, W1l);
    tsplit_kernel<<<dim3(DIM / 32, HID / 32), tb>>>(W2,  HID, DIM, W2h, W2l);
    tsplit_kernel<<<dim3(HV  / 32, DIM / 32), tb>>>(Wv1, DIM, HV,  V1h, V1l);
    tsplit_kernel<<<dim3(VO  / 32, HV  / 32), tb>>>(Wv2, HV,  VO,  V2h, 0);
    // x split
    xsplit_kernel<<<(BATCH * DIM / 4 + 255) / 256, 256>>>(x, xhi, xlo);

    // GEMM1: H1(hi/lo) = tanh(x@W1 + b1)        [3-pass]
    tgemm<3, 1|2|8><<<dim3(HID / 128, BATCH / 128), 256, 98304>>>(
        HID, DIM, xhi, xlo, W1h, W1l, b1, 0, H1hi, H1lo);
    // GEMM2: FH(f32 + hi/lo) = H1@W2 + b2       [3-pass]
    tgemm<3, 2|4|8><<<dim3(DIM / 128, BATCH / 128), 256, 98304>>>(
        DIM, HID, H1hi, H1lo, W2h, W2l, b2, FH, FHhi, FHlo);
    // GEMM3: HX(hi) = tanh(x@Wv1)               [1-pass]
    tgemm<1, 1|16><<<dim3(HV / 128, BATCH / 128), 256, 65536>>>(
        HV, DIM, xhi, 0, V1h, 0, 0, 0, HXhi, 0);
    // GEMM4: Yx = HX@Wv2                        [1-pass]
    tgemm<1, 4><<<dim3(VO / 128, BATCH / 128), 256, 65536>>>(
        VO, HV, HXhi, 0, V2h, 0, 0, Yx, 0, 0);
    // GEMM5: U(f32) = FH@Wv1, T(hi)=tanh(U)     [1-pass, dual output]
    tgemm<1, 4|32><<<dim3(HV / 128, BATCH / 128), 256, 65536>>>(
        HV, DIM, FHhi, 0, V1h, 0, 0, U, Thi, 0);
    // GEMM6: Y1 = T@Wv2                         [1-pass]  (alpha=1 residual)
    tgemm<1, 4><<<dim3(VO / 128, BATCH / 128), 256, 65536>>>(
        VO, HV, Thi, 0, V2h, 0, 0, Y1, 0, 0);

    reduce_kernel<<<BATCH / 8, 256>>>(x);
    newton_kernel<<<BATCH / NG, 256>>>(Wv2);
    scale_out_kernel<<<(BATCH * (DIM / 4) + 255) / 256, 256>>>(out);
}